// round 2
// baseline (speedup 1.0000x reference)
#include <cuda_runtime.h>

#define NMAX 100000
#define EMAX 1600000
#define H 64
#define EDIM 9
#define NEG_SLOPE 0.2f

// ---------------- scratch (device globals; allocation-free) ----------------
__device__ __align__(16) float g_h[(size_t)NMAX * H];      // h = x @ W
__device__ __align__(16) float g_out[(size_t)NMAX * H];    // segment-sum accumulator
__device__ float g_asrc[NMAX];
__device__ float g_adst[NMAX];
__device__ float g_deg[NMAX];
__device__ float g_loopsum[(size_t)NMAX * EDIM];
__device__ unsigned g_amaxkey[NMAX];
__device__ float g_amaxf[NMAX];
__device__ float g_alpha[EMAX];                            // leaky(alpha) then exp(..)
__device__ float g_denom[NMAX];
__device__ float g_exloop[NMAX];
__device__ float g_p[NMAX];
__device__ float g_we[EDIM];                               // W_edge @ att_edge

// monotone float<->uint key for atomicMax (memset-0 == -inf sentinel)
__device__ __forceinline__ unsigned fkey(float f) {
    unsigned u = __float_as_uint(f);
    return (u & 0x80000000u) ? ~u : (u | 0x80000000u);
}
__device__ __forceinline__ float funkey(unsigned k) {
    return (k & 0x80000000u) ? __uint_as_float(k & 0x7FFFFFFFu)
                             : __uint_as_float(~k);
}

// K0: w_e[j] = sum_k W_edge[j,k] * att_edge[k]
__global__ void k0_we(const float* __restrict__ W_edge,
                      const float* __restrict__ att_edge) {
    int j = threadIdx.x;
    if (j < EDIM) {
        float s = 0.f;
        #pragma unroll
        for (int k = 0; k < H; k++) s += W_edge[j * H + k] * att_edge[k];
        g_we[j] = s;
    }
}

// K1: per-node h = x @ W, a_src = h.att_src, a_dst = h.att_dst. Warp per node.
__global__ void k1_nodes(const float* __restrict__ x, const float* __restrict__ W,
                         const float* __restrict__ att_src,
                         const float* __restrict__ att_dst, int n) {
    __shared__ float sW[16 * H];
    for (int t = threadIdx.x; t < 16 * H; t += blockDim.x) sW[t] = W[t];
    __syncthreads();
    int node = (int)((blockIdx.x * (unsigned)blockDim.x + threadIdx.x) >> 5);
    int lane = threadIdx.x & 31;
    if (node >= n) return;
    float xv = (lane < 16) ? x[(size_t)node * 16 + lane] : 0.f;
    float h0 = 0.f, h1 = 0.f;
    #pragma unroll
    for (int k = 0; k < 16; k++) {
        float xk = __shfl_sync(0xffffffffu, xv, k);
        h0 += xk * sW[k * H + 2 * lane];
        h1 += xk * sW[k * H + 2 * lane + 1];
    }
    *(float2*)&g_h[(size_t)node * H + 2 * lane] = make_float2(h0, h1);
    float ps = h0 * att_src[2 * lane] + h1 * att_src[2 * lane + 1];
    float pd = h0 * att_dst[2 * lane] + h1 * att_dst[2 * lane + 1];
    #pragma unroll
    for (int o = 16; o > 0; o >>= 1) {
        ps += __shfl_xor_sync(0xffffffffu, ps, o);
        pd += __shfl_xor_sync(0xffffffffu, pd, o);
    }
    if (lane == 0) { g_asrc[node] = ps; g_adst[node] = pd; }
}

// K2: per original edge: alpha=leaky(a_src[s]+a_dst[d]+ea.w_e); seg-max;
//     accumulate deg + incoming edge_attr for self-loop fill.
__global__ void k2_edges(const float* __restrict__ ea,
                         const int* __restrict__ src,
                         const int* __restrict__ dst, int E) {
    int e = blockIdx.x * blockDim.x + threadIdx.x;
    if (e >= E) return;
    int s = src[e], d = dst[e];
    float v[EDIM];
    float aedge = 0.f;
    #pragma unroll
    for (int j = 0; j < EDIM; j++) {
        v[j] = ea[(size_t)e * EDIM + j];
        aedge += v[j] * g_we[j];
    }
    float a = g_asrc[s] + g_adst[d] + aedge;
    a = (a >= 0.f) ? a : NEG_SLOPE * a;
    g_alpha[e] = a;
    atomicMax(&g_amaxkey[d], fkey(a));
    atomicAdd(&g_deg[d], 1.f);
    #pragma unroll
    for (int j = 0; j < EDIM; j++)
        atomicAdd(&g_loopsum[(size_t)d * EDIM + j], v[j]);
}

// K3: per node: self-loop alpha (mean edge_attr), finalize max, seed denom.
__global__ void k3_nodes(int n) {
    int i = blockIdx.x * blockDim.x + threadIdx.x;
    if (i >= n) return;
    float inv = 1.f / fmaxf(g_deg[i], 1.f);
    float aedge = 0.f;
    #pragma unroll
    for (int j = 0; j < EDIM; j++)
        aedge += g_loopsum[(size_t)i * EDIM + j] * inv * g_we[j];
    float a = g_asrc[i] + g_adst[i] + aedge;
    a = (a >= 0.f) ? a : NEG_SLOPE * a;
    unsigned k = g_amaxkey[i];
    unsigned ka = fkey(a);
    if (ka > k) k = ka;
    float amax = funkey(k);
    g_amaxf[i] = amax;
    float exl = __expf(a - amax);
    g_exloop[i] = exl;
    g_denom[i] = exl;   // self-loop contribution seeds the denom (no memset needed)
}

// K4: per edge: ex = exp(alpha - amax[dst]); denom[dst] += ex
__global__ void k4_edges(const int* __restrict__ dst, int E) {
    int e = blockIdx.x * blockDim.x + threadIdx.x;
    if (e >= E) return;
    int d = dst[e];
    float ex = __expf(g_alpha[e] - g_amaxf[d]);
    g_alpha[e] = ex;
    atomicAdd(&g_denom[d], ex);
}

// K5: message scatter. Half-warp (16 lanes) per edge, float4 per lane,
//     vectorized red.global.add.v4.f32 (sm_90+).
__global__ void k5_msg(const int* __restrict__ src,
                       const int* __restrict__ dst, int E) {
    unsigned t = blockIdx.x * blockDim.x + threadIdx.x;
    int e = (int)(t >> 4);
    int l = (int)(t & 15);
    if (e >= E) return;
    int s = src[e], d = dst[e];
    float an = g_alpha[e] / (g_denom[d] + 1e-16f);
    float4 hv = *(const float4*)&g_h[(size_t)s * H + l * 4];
    float4 m = make_float4(hv.x * an, hv.y * an, hv.z * an, hv.w * an);
    float* p = &g_out[(size_t)d * H + l * 4];
    asm volatile("red.global.add.v4.f32 [%0], {%1, %2, %3, %4};"
                 :: "l"(p), "f"(m.x), "f"(m.y), "f"(m.z), "f"(m.w)
                 : "memory");
}

// K6: per node: add self-loop msg, +bias, relu, p = x2 . lin_w. Warp per node.
__global__ void k6_nodes(const float* __restrict__ bias,
                         const float* __restrict__ lin_w, int n) {
    int node = (int)((blockIdx.x * (unsigned)blockDim.x + threadIdx.x) >> 5);
    int lane = threadIdx.x & 31;
    if (node >= n) return;
    float sc = g_exloop[node] / (g_denom[node] + 1e-16f);
    float2 hv  = *(const float2*)&g_h[(size_t)node * H + 2 * lane];
    float2 acc = *(const float2*)&g_out[(size_t)node * H + 2 * lane];
    float v0 = fmaxf(acc.x + hv.x * sc + bias[2 * lane], 0.f);
    float v1 = fmaxf(acc.y + hv.y * sc + bias[2 * lane + 1], 0.f);
    float pp = v0 * lin_w[2 * lane] + v1 * lin_w[2 * lane + 1];
    #pragma unroll
    for (int o = 16; o > 0; o >>= 1)
        pp += __shfl_xor_sync(0xffffffffu, pp, o);
    if (lane == 0) g_p[node] = pp;
}

// K7: per original edge: sigmoid(0.5*(p[src]+p[dst]) + lin_b)
__global__ void k7_out(const int* __restrict__ src,
                       const int* __restrict__ dst,
                       const float* __restrict__ lin_b,
                       float* __restrict__ out, int E) {
    int e = blockIdx.x * blockDim.x + threadIdx.x;
    if (e >= E) return;
    float z = 0.5f * (g_p[src[e]] + g_p[dst[e]]) + lin_b[0];
    out[e] = 1.f / (1.f + __expf(-z));
}

extern "C" void kernel_launch(void* const* d_in, const int* in_sizes, int n_in,
                              void* d_out, int out_size) {
    const float* x        = (const float*)d_in[0];
    const float* ea       = (const float*)d_in[1];
    const float* W        = (const float*)d_in[2];
    const float* W_edge   = (const float*)d_in[3];
    const float* att_src  = (const float*)d_in[4];
    const float* att_dst  = (const float*)d_in[5];
    const float* att_edge = (const float*)d_in[6];
    const float* bias     = (const float*)d_in[7];
    const float* lin_w    = (const float*)d_in[8];
    const float* lin_b    = (const float*)d_in[9];
    const int*   ei       = (const int*)d_in[10];   // JAX default x64-disabled: int32

    int n = in_sizes[0] / 16;
    int E = in_sizes[1] / EDIM;
    const int* src = ei;
    const int* dst = ei + E;

    void *p_deg, *p_loop, *p_amax, *p_out;
    cudaGetSymbolAddress(&p_deg, g_deg);
    cudaGetSymbolAddress(&p_loop, g_loopsum);
    cudaGetSymbolAddress(&p_amax, g_amaxkey);
    cudaGetSymbolAddress(&p_out, g_out);
    cudaMemsetAsync(p_deg,  0, (size_t)n * 4, 0);
    cudaMemsetAsync(p_loop, 0, (size_t)n * EDIM * 4, 0);
    cudaMemsetAsync(p_amax, 0, (size_t)n * 4, 0);            // 0 == -inf key
    cudaMemsetAsync(p_out,  0, (size_t)n * H * 4, 0);

    k0_we   <<<1, 64>>>(W_edge, att_edge);
    k1_nodes<<<(n + 7) / 8, 256>>>(x, W, att_src, att_dst, n);
    k2_edges<<<(E + 255) / 256, 256>>>(ea, src, dst, E);
    k3_nodes<<<(n + 255) / 256, 256>>>(n);
    k4_edges<<<(E + 255) / 256, 256>>>(dst, E);
    k5_msg  <<<((size_t)E * 16 + 255) / 256, 256>>>(src, dst, E);
    k6_nodes<<<(n + 7) / 8, 256>>>(bias, lin_w, n);
    k7_out  <<<(E + 255) / 256, 256>>>(src, dst, lin_b, (float*)d_out, E);
}

// round 3
// speedup vs baseline: 1.2867x; 1.2867x over previous
#include <cuda_runtime.h>

#define NMAX 100000
#define EMAX 1600000
#define H 64
#define EDIM 9
#define NEG_SLOPE 0.2f

// ---------------- scratch (device globals; allocation-free) ----------------
__device__ __align__(16) float g_h[(size_t)NMAX * H];    // h = x @ W
__device__ __align__(16) float g_out[(size_t)NMAX * H];  // segment-sum accumulator
__device__ __align__(16) float g_nd[(size_t)NMAX * 4];   // {denom, aesum, deg, pad}
__device__ float g_asrc[NMAX];
__device__ float g_adst[NMAX];
__device__ float g_alpha[EMAX];                          // exp(leaky(alpha))
__device__ float g_exloop[NMAX];
__device__ float g_p[NMAX];

// K1: per-node h = x @ W, a_src = h.att_src, a_dst = h.att_dst. Warp per node.
__global__ void k1_nodes(const float* __restrict__ x, const float* __restrict__ W,
                         const float* __restrict__ att_src,
                         const float* __restrict__ att_dst, int n) {
    __shared__ float sW[16 * H];
    for (int t = threadIdx.x; t < 16 * H; t += blockDim.x) sW[t] = W[t];
    __syncthreads();
    int node = (int)((blockIdx.x * (unsigned)blockDim.x + threadIdx.x) >> 5);
    int lane = threadIdx.x & 31;
    if (node >= n) return;
    float xv = (lane < 16) ? x[(size_t)node * 16 + lane] : 0.f;
    float h0 = 0.f, h1 = 0.f;
    #pragma unroll
    for (int k = 0; k < 16; k++) {
        float xk = __shfl_sync(0xffffffffu, xv, k);
        h0 += xk * sW[k * H + 2 * lane];
        h1 += xk * sW[k * H + 2 * lane + 1];
    }
    *(float2*)&g_h[(size_t)node * H + 2 * lane] = make_float2(h0, h1);
    float ps = h0 * att_src[2 * lane] + h1 * att_src[2 * lane + 1];
    float pd = h0 * att_dst[2 * lane] + h1 * att_dst[2 * lane + 1];
    #pragma unroll
    for (int o = 16; o > 0; o >>= 1) {
        ps += __shfl_xor_sync(0xffffffffu, ps, o);
        pd += __shfl_xor_sync(0xffffffffu, pd, o);
    }
    if (lane == 0) { g_asrc[node] = ps; g_adst[node] = pd; }
}

// K2: per edge: a_edge = ea.w_e ; alpha = exp(leaky(a_src+a_dst+a_edge));
//     single red.v4 accumulates {exp, a_edge, 1, 0} into g_nd[dst].
__global__ void k2_edges(const float* __restrict__ ea,
                         const int* __restrict__ src,
                         const int* __restrict__ dst,
                         const float* __restrict__ W_edge,
                         const float* __restrict__ att_edge, int E) {
    __shared__ float sWE[EDIM];
    __shared__ __align__(16) float sEA[256 * EDIM];
    if (threadIdx.x < EDIM) {
        float s = 0.f;
        #pragma unroll
        for (int k = 0; k < H; k++) s += W_edge[threadIdx.x * H + k] * att_edge[k];
        sWE[threadIdx.x] = s;
    }
    int base = blockIdx.x * 256;
    int nE = min(256, E - base);
    const float* gea = ea + (size_t)base * EDIM;
    if (nE == 256) {
        const float4* g4 = (const float4*)gea;   // 9216B block: float4-aligned
        float4* s4 = (float4*)sEA;
        #pragma unroll
        for (int t = threadIdx.x; t < 576; t += 256) s4[t] = g4[t];
    } else {
        for (int t = threadIdx.x; t < nE * EDIM; t += 256) sEA[t] = gea[t];
    }
    __syncthreads();
    if (threadIdx.x >= nE) return;
    int e = base + threadIdx.x;
    const float* v = &sEA[threadIdx.x * EDIM];
    float aedge = 0.f;
    #pragma unroll
    for (int j = 0; j < EDIM; j++) aedge += v[j] * sWE[j];
    int s = src[e], d = dst[e];
    float a = g_asrc[s] + g_adst[d] + aedge;
    a = (a >= 0.f) ? a : NEG_SLOPE * a;
    float ex = __expf(a);          // unstabilized: alpha is O(1), exp is safe
    g_alpha[e] = ex;
    float* p = &g_nd[(size_t)d * 4];
    asm volatile("red.global.add.v4.f32 [%0], {%1, %2, %3, %4};"
                 :: "l"(p), "f"(ex), "f"(aedge), "f"(1.0f), "f"(0.0f)
                 : "memory");
}

// K3: per node: self-loop alpha from mean a_edge; add its exp into denom.
__global__ void k3_nodes(int n) {
    int i = blockIdx.x * blockDim.x + threadIdx.x;
    if (i >= n) return;
    float4 nd = *(float4*)&g_nd[(size_t)i * 4];   // {denom, aesum, deg, _}
    float aedge = nd.y / fmaxf(nd.z, 1.f);
    float a = g_asrc[i] + g_adst[i] + aedge;
    a = (a >= 0.f) ? a : NEG_SLOPE * a;
    float exl = __expf(a);
    g_exloop[i] = exl;
    g_nd[(size_t)i * 4] = nd.x + exl;             // finalize denom
}

// K5: message scatter. Half-warp (16 lanes) per edge, float4 per lane,
//     vectorized red.global.add.v4.f32.
__global__ void k5_msg(const int* __restrict__ src,
                       const int* __restrict__ dst, int E) {
    unsigned t = blockIdx.x * blockDim.x + threadIdx.x;
    int e = (int)(t >> 4);
    int l = (int)(t & 15);
    if (e >= E) return;
    int s = src[e], d = dst[e];
    float an = g_alpha[e] / (g_nd[(size_t)d * 4] + 1e-16f);
    float4 hv = *(const float4*)&g_h[(size_t)s * H + l * 4];
    float4 m = make_float4(hv.x * an, hv.y * an, hv.z * an, hv.w * an);
    float* p = &g_out[(size_t)d * H + l * 4];
    asm volatile("red.global.add.v4.f32 [%0], {%1, %2, %3, %4};"
                 :: "l"(p), "f"(m.x), "f"(m.y), "f"(m.z), "f"(m.w)
                 : "memory");
}

// K6: per node: add self-loop msg, +bias, relu, p = x2 . lin_w. Warp per node.
__global__ void k6_nodes(const float* __restrict__ bias,
                         const float* __restrict__ lin_w, int n) {
    int node = (int)((blockIdx.x * (unsigned)blockDim.x + threadIdx.x) >> 5);
    int lane = threadIdx.x & 31;
    if (node >= n) return;
    float sc = g_exloop[node] / (g_nd[(size_t)node * 4] + 1e-16f);
    float2 hv  = *(const float2*)&g_h[(size_t)node * H + 2 * lane];
    float2 acc = *(const float2*)&g_out[(size_t)node * H + 2 * lane];
    float v0 = fmaxf(acc.x + hv.x * sc + bias[2 * lane], 0.f);
    float v1 = fmaxf(acc.y + hv.y * sc + bias[2 * lane + 1], 0.f);
    float pp = v0 * lin_w[2 * lane] + v1 * lin_w[2 * lane + 1];
    #pragma unroll
    for (int o = 16; o > 0; o >>= 1)
        pp += __shfl_xor_sync(0xffffffffu, pp, o);
    if (lane == 0) g_p[node] = pp;
}

// K7: per original edge: sigmoid(0.5*(p[src]+p[dst]) + lin_b)
__global__ void k7_out(const int* __restrict__ src,
                       const int* __restrict__ dst,
                       const float* __restrict__ lin_b,
                       float* __restrict__ out, int E) {
    int e = blockIdx.x * blockDim.x + threadIdx.x;
    if (e >= E) return;
    float z = 0.5f * (g_p[src[e]] + g_p[dst[e]]) + lin_b[0];
    out[e] = 1.f / (1.f + __expf(-z));
}

extern "C" void kernel_launch(void* const* d_in, const int* in_sizes, int n_in,
                              void* d_out, int out_size) {
    const float* x        = (const float*)d_in[0];
    const float* ea       = (const float*)d_in[1];
    const float* W        = (const float*)d_in[2];
    const float* W_edge   = (const float*)d_in[3];
    const float* att_src  = (const float*)d_in[4];
    const float* att_dst  = (const float*)d_in[5];
    const float* att_edge = (const float*)d_in[6];
    const float* bias     = (const float*)d_in[7];
    const float* lin_w    = (const float*)d_in[8];
    const float* lin_b    = (const float*)d_in[9];
    const int*   ei       = (const int*)d_in[10];   // int32 (JAX x64 disabled)

    int n = in_sizes[0] / 16;
    int E = in_sizes[1] / EDIM;
    const int* src = ei;
    const int* dst = ei + E;

    void *p_nd, *p_out;
    cudaGetSymbolAddress(&p_nd, g_nd);
    cudaGetSymbolAddress(&p_out, g_out);
    cudaMemsetAsync(p_nd,  0, (size_t)n * 4 * 4, 0);
    cudaMemsetAsync(p_out, 0, (size_t)n * H * 4, 0);

    k1_nodes<<<(n + 7) / 8, 256>>>(x, W, att_src, att_dst, n);
    k2_edges<<<(E + 255) / 256, 256>>>(ea, src, dst, W_edge, att_edge, E);
    k3_nodes<<<(n + 255) / 256, 256>>>(n);
    k5_msg  <<<((size_t)E * 16 + 255) / 256, 256>>>(src, dst, E);
    k6_nodes<<<(n + 7) / 8, 256>>>(bias, lin_w, n);
    k7_out  <<<(E + 255) / 256, 256>>>(src, dst, lin_b, (float*)d_out, E);
}